// round 15
// baseline (speedup 1.0000x reference)
#include <cuda_runtime.h>
#include <cuda_fp16.h>
#include <math.h>
#include <stdint.h>

#define Bb 8
#define Ss 1024
#define Dd 1024
#define Hh 16
#define HDIM 64
#define Ff 4096
#define Mm (Bb*Ss)

// ---------------------------------------------------------------------------
// Scratch (device globals). All GEMM operands single-plane fp16.
// ---------------------------------------------------------------------------
__device__ __half g_qh [(size_t)Mm*Dd];
__device__ __half g_kh [(size_t)Mm*Dd];
__device__ __half g_vh [(size_t)Mm*Dd];
__device__ __half g_Qh [(size_t)Mm*Dd];
__device__ __half g_Kh [(size_t)Mm*Dd];
__device__ __half g_Vh [(size_t)Mm*Dd];
__device__ __half g_Vth[(size_t)Bb*Hh*HDIM*Ss];
__device__ __half g_cth[(size_t)Mm*Dd];
__device__ __half g_aoh[(size_t)Mm*Dd];
__device__ __half g_Fh [(size_t)Mm*Ff];
__device__ __half g_Sh [(size_t)Bb*Hh*Ss*Ss];      // scores fp16 (post-mask)
__device__ float  g_sm [(size_t)Bb*Hh*Ss];         // per-row max
__device__ float  g_sl [(size_t)Bb*Hh*Ss];         // per-row 1/sum
__device__ __half g_WT [(size_t)(4*Dd*Dd + Dd*Ff + Ff*Dd)];
__device__ float  g_X  [(size_t)Mm*Dd];
__device__ float  g_ao [(size_t)Mm*Dd];
__device__ float  g_Z  [(size_t)Mm*Dd];

// ---------------------------------------------------------------------------
// PTX helpers
// ---------------------------------------------------------------------------
__device__ __forceinline__ uint32_t smem_u32(const void* p) {
    uint32_t a;
    asm("{ .reg .u64 t; cvta.to.shared.u64 t, %1; cvt.u32.u64 %0, t; }"
        : "=r"(a) : "l"(p));
    return a;
}
__device__ __forceinline__ void ldsm4(uint32_t& r0, uint32_t& r1, uint32_t& r2,
                                      uint32_t& r3, uint32_t addr) {
    asm volatile("ldmatrix.sync.aligned.m8n8.x4.shared.b16 {%0,%1,%2,%3}, [%4];"
                 : "=r"(r0), "=r"(r1), "=r"(r2), "=r"(r3) : "r"(addr));
}
__device__ __forceinline__ void mma16816(float* d, const uint32_t* a,
                                         const uint32_t* b) {
    asm volatile(
        "mma.sync.aligned.m16n8k16.row.col.f32.f16.f16.f32 "
        "{%0,%1,%2,%3}, {%4,%5,%6,%7}, {%8,%9}, {%0,%1,%2,%3};"
        : "+f"(d[0]), "+f"(d[1]), "+f"(d[2]), "+f"(d[3])
        : "r"(a[0]), "r"(a[1]), "r"(a[2]), "r"(a[3]), "r"(b[0]), "r"(b[1]));
}
__device__ __forceinline__ void cpa16(uint32_t dst, const void* src) {
    asm volatile("cp.async.cg.shared.global [%0], [%1], 16;"
                 :: "r"(dst), "l"(src) : "memory");
}
#define CP_COMMIT() asm volatile("cp.async.commit_group;" ::: "memory")
#define CP_WAIT0()  asm volatile("cp.async.wait_group 0;" ::: "memory")
#define CP_WAIT1()  asm volatile("cp.async.wait_group 1;" ::: "memory")

__device__ __forceinline__ uint32_t packh2(float a, float b) {
    __half2 h = __floats2half2_rn(a, b);
    return *(uint32_t*)&h;
}

// ---------------------------------------------------------------------------
// GEMM: C[64 x BN] = A[64,K] @ B[BN,K]^T, fp32 accum, fp16 operands.
//   CTA tile 64 x 128, warp grid 2(m) x 4(n), warp tile 32x32 (MF=2, NF=4).
//   BK=64 chunks, 2-stage cp.async, 1 sync/chunk, 3 CTAs/SM (occupancy).
//   EPI: 0=+bias  1=+bias,relu ; CFMT: 0 = fp32 out ; 2 = fp16 out
// ---------------------------------------------------------------------------
template<int BN, int EPI, int CFMT>
__global__ void __launch_bounds__(256, 3) gemm_ps(
    const __half* __restrict__ AH,
    long long lda,
    const __half* __restrict__ BH,
    long long ldb,
    float* __restrict__ C, __half* __restrict__ CH,
    long long ldc,
    const float* __restrict__ aux, int K)
{
    constexpr int MF = 2;
    constexpr int NF = BN / 32;
    constexpr int ABLK = 64 * 80;        // 64 rows x 80 B
    constexpr int BBLK = BN * 80;
    constexpr int STAGE = 2 * ABLK + 2 * BBLK;

    extern __shared__ char dsm[];

    const int tid = threadIdx.x, lane = tid & 31, wid = tid >> 5;
    const int row0 = blockIdx.y * 64, col0 = blockIdx.x * BN;
    const int m0w = (wid >> 2) * 32, n0w = (wid & 3) * (BN / 4);

    const __half* Abh = AH + (size_t)row0 * lda;
    const __half* Bbh = BH + (size_t)col0 * ldb;

    const uint32_t sbase = smem_u32(dsm);

    float acc[MF][NF][4];
#pragma unroll
    for (int i = 0; i < MF; i++)
#pragma unroll
        for (int j = 0; j < NF; j++)
#pragma unroll
            for (int k = 0; k < 4; k++) acc[i][j][k] = 0.f;

    // Loads 64 K-cols (two 32-col blocks) into stage st.
    auto issue = [&](int st, int k0) {
        uint32_t base = sbase + st * STAGE;
#pragma unroll
        for (int i = 0; i < 2; i++) {        // A: 64 rows x 8 16B-groups
            int q = tid + i * 256;
            int r = q >> 3, g = q & 7;
            int blk = g >> 2, gg = g & 3;
            cpa16(base + blk * ABLK + r * 80 + gg * 16,
                  Abh + (size_t)r * lda + k0 + g * 8);
        }
#pragma unroll
        for (int i = 0; i < NF; i++) {       // B: BN rows x 8 groups
            int q = tid + i * 256;
            int r = q >> 3, g = q & 7;
            int blk = g >> 2, gg = g & 3;
            cpa16(base + 2 * ABLK + blk * BBLK + r * 80 + gg * 16,
                  Bbh + (size_t)r * ldb + k0 + g * 8);
        }
        CP_COMMIT();
    };

    const int NCH = K >> 6;
    issue(0, 0);

    for (int c = 0; c < NCH; c++) {
        CP_WAIT0();
        __syncthreads();
        if (c + 1 < NCH) issue((c + 1) & 1, (c + 1) * 64);

        const uint32_t stg = sbase + (c & 1) * STAGE;
#pragma unroll
        for (int j = 0; j < 2; j++) {
            const uint32_t aAh = stg + j * ABLK;
            const uint32_t aBh = stg + 2 * ABLK + j * BBLK;
#pragma unroll
            for (int kk = 0; kk < 32; kk += 16) {
                uint32_t bh[NF][2];
#pragma unroll
                for (int np = 0; np < NF / 2; np++) {
                    uint32_t bo = (uint32_t)((n0w + np * 16 + ((lane >> 4) << 3) +
                                              (lane & 7)) * 40 +
                                             kk + ((lane >> 3) & 1) * 8) * 2;
                    ldsm4(bh[2 * np][0], bh[2 * np][1], bh[2 * np + 1][0],
                          bh[2 * np + 1][1], aBh + bo);
                }
#pragma unroll
                for (int mi = 0; mi < MF; mi++) {
                    uint32_t ao = (uint32_t)((m0w + mi * 16 + (lane & 15)) * 40 +
                                             kk + ((lane >> 4) << 3)) * 2;
                    uint32_t ah[4];
                    ldsm4(ah[0], ah[1], ah[2], ah[3], aAh + ao);
#pragma unroll
                    for (int ni = 0; ni < NF; ni++)
                        mma16816(acc[mi][ni], ah, bh[ni]);
                }
            }
        }
    }
    __syncthreads();

#pragma unroll
    for (int ni = 0; ni < NF; ni++) {
        const int col = col0 + n0w + ni * 8 + (lane & 3) * 2;
        float2 e = *(const float2*)(aux + col);
#pragma unroll
        for (int mi = 0; mi < MF; mi++) {
            const int r0g = row0 + m0w + mi * 16 + (lane >> 2);
            float* a = acc[mi][ni];
            float2 v0 = make_float2(a[0] + e.x, a[1] + e.y);
            float2 v1 = make_float2(a[2] + e.x, a[3] + e.y);
            if (EPI == 1) {
                v0.x = fmaxf(v0.x, 0.f); v0.y = fmaxf(v0.y, 0.f);
                v1.x = fmaxf(v1.x, 0.f); v1.y = fmaxf(v1.y, 0.f);
            }
            if (CFMT == 0) {
                *(float2*)(C + (size_t)r0g * ldc + col) = v0;
                *(float2*)(C + (size_t)(r0g + 8) * ldc + col) = v1;
            } else {
                *(__half2*)(CH + (size_t)r0g * ldc + col) =
                    __floats2half2_rn(v0.x, v0.y);
                *(__half2*)(CH + (size_t)(r0g + 8) * ldc + col) =
                    __floats2half2_rn(v1.x, v1.y);
            }
        }
    }
}

// ---------------------------------------------------------------------------
// Flash attention: scores + online softmax + PV, one CTA = 128 q-rows of one
// (b,h). 8 warps, warp tile = 16 rows x full width (row stats warp-local).
// Writes: Sh (post-mask scores fp16), cth (context fp16),
//         sm/sl (per-row max and 1/sum for the finalize kernel).
// ---------------------------------------------------------------------------
__global__ void __launch_bounds__(256, 1) flash_attn(
    const __half* __restrict__ Qh, const __half* __restrict__ Kh,
    const __half* __restrict__ Vth, const float* __restrict__ mask,
    __half* __restrict__ Sh, __half* __restrict__ cth,
    float* __restrict__ sm, float* __restrict__ sl)
{
    constexpr int TW = 128;    // kv tile width
    constexpr int DST = 72;    // Q/K smem row stride (halves)
    constexpr int VST = 136;   // V smem row stride (halves)

    extern __shared__ char dsm[];
    __half* Qs  = (__half*)dsm;                                   // 18432 B
    __half* Ks0 = (__half*)(dsm + 18432);                         // 2x18432
    __half* Vs0 = (__half*)(dsm + 18432 + 2 * 18432);             // 2x17408
    float* madd = (float*)(dsm + 18432 + 2 * 18432 + 2 * 17408);  // 4096

    const int tid = threadIdx.x, lane = tid & 31, wid = tid >> 5;
    const int bh = blockIdx.y, b = bh >> 4, h = bh & 15;
    const int q0 = blockIdx.x * 128;

    const __half* Qb = Qh + (size_t)b * Ss * Dd + (size_t)h * HDIM + (size_t)q0 * Dd;
    const __half* Kb = Kh + (size_t)b * Ss * Dd + (size_t)h * HDIM;
    const __half* Vb = Vth + (size_t)bh * HDIM * Ss;
    __half* Shb = Sh + (size_t)bh * Ss * Ss + (size_t)q0 * Ss;
    __half* Cb  = cth + (size_t)b * Ss * Dd + (size_t)h * HDIM + (size_t)q0 * Dd;

    {
        float4 mv = *(const float4*)(mask + (size_t)b * Ss + tid * 4);
        madd[tid * 4 + 0] = (1.f - mv.x) * -10000.f;
        madd[tid * 4 + 1] = (1.f - mv.y) * -10000.f;
        madd[tid * 4 + 2] = (1.f - mv.z) * -10000.f;
        madd[tid * 4 + 3] = (1.f - mv.w) * -10000.f;
    }

    auto issueKV = [&](int st, int t) {
        __half* kd = Ks0 + st * (DST * 128);
        const __half* ks = Kb + (size_t)(t * TW) * Dd;
#pragma unroll
        for (int i = 0; i < 4; i++) {
            int q = tid + i * 256;
            int r = q >> 3, g = q & 7;
            cpa16(smem_u32(kd + r * DST + g * 8), ks + (size_t)r * Dd + g * 8);
        }
        __half* vd = Vs0 + st * (VST * 64);
#pragma unroll
        for (int i = 0; i < 4; i++) {
            int q = tid + i * 256;
            int r = q >> 4, g = q & 15;
            cpa16(smem_u32(vd + r * VST + g * 8),
                  Vb + (size_t)r * Ss + t * TW + g * 8);
        }
        CP_COMMIT();
    };

#pragma unroll
    for (int i = 0; i < 4; i++) {
        int q = tid + i * 256;
        int r = q >> 3, g = q & 7;
        cpa16(smem_u32(Qs + r * DST + g * 8), Qb + (size_t)r * Dd + g * 8);
    }
    issueKV(0, 0);
    issueKV(1, 1);

    const int r0w = wid * 16;
    const uint32_t qbase = smem_u32(Qs);

    float m0 = -1e30f, m1 = -1e30f, l0 = 0.f, l1 = 0.f;
    float acco[8][4];
#pragma unroll
    for (int i = 0; i < 8; i++)
#pragma unroll
        for (int j = 0; j < 4; j++) acco[i][j] = 0.f;

    const int NT = Ss / TW;  // 8
    for (int t = 0; t < NT; t++) {
        if (t + 1 < NT) CP_WAIT1(); else CP_WAIT0();
        __syncthreads();

        const uint32_t kbase = smem_u32(Ks0 + (t & 1) * (DST * 128));
        const uint32_t vbase = smem_u32(Vs0 + (t & 1) * (VST * 64));

        float accs[16][4];
#pragma unroll
        for (int i = 0; i < 16; i++)
#pragma unroll
            for (int j = 0; j < 4; j++) accs[i][j] = 0.f;

#pragma unroll
        for (int kk = 0; kk < 64; kk += 16) {
            uint32_t ah[4];
            ldsm4(ah[0], ah[1], ah[2], ah[3],
                  qbase + (uint32_t)((r0w + (lane & 15)) * DST + kk +
                                     ((lane >> 4) << 3)) * 2);
#pragma unroll
            for (int np = 0; np < 8; np++) {
                uint32_t b0, b1, b2, b3;
                ldsm4(b0, b1, b2, b3,
                      kbase + (uint32_t)((np * 16 + ((lane >> 4) << 3) +
                                          (lane & 7)) * DST + kk +
                                         ((lane >> 3) & 1) * 8) * 2);
                uint32_t bf0[2] = { b0, b1 }, bf1[2] = { b2, b3 };
                mma16816(accs[2 * np], ah, bf0);
                mma16816(accs[2 * np + 1], ah, bf1);
            }
        }

        float mx0 = -1e30f, mx1 = -1e30f;
#pragma unroll
        for (int ni = 0; ni < 16; ni++) {
            int col = t * TW + ni * 8 + (lane & 3) * 2;
            float e0 = madd[col], e1 = madd[col + 1];
            accs[ni][0] = accs[ni][0] * 0.125f + e0;
            accs[ni][1] = accs[ni][1] * 0.125f + e1;
            accs[ni][2] = accs[ni][2] * 0.125f + e0;
            accs[ni][3] = accs[ni][3] * 0.125f + e1;
            mx0 = fmaxf(mx0, fmaxf(accs[ni][0], accs[ni][1]));
            mx1 = fmaxf(mx1, fmaxf(accs[ni][2], accs[ni][3]));
        }
        mx0 = fmaxf(mx0, __shfl_xor_sync(~0u, mx0, 1));
        mx0 = fmaxf(mx0, __shfl_xor_sync(~0u, mx0, 2));
        mx1 = fmaxf(mx1, __shfl_xor_sync(~0u, mx1, 1));
        mx1 = fmaxf(mx1, __shfl_xor_sync(~0u, mx1, 2));

        {
            const int row = r0w + (lane >> 2);
#pragma unroll
            for (int ni = 0; ni < 16; ni++) {
                int col = t * TW + ni * 8 + (lane & 3) * 2;
                *(__half2*)(Shb + (size_t)row * Ss + col) =
                    __floats2half2_rn(accs[ni][0], accs[ni][1]);
                *(__half2*)(Shb + (size_t)(row + 8) * Ss + col) =
                    __floats2half2_rn(accs[ni][2], accs[ni][3]);
            }
        }

        float mn0 = fmaxf(m0, mx0), mn1 = fmaxf(m1, mx1);
        float rs0 = __expf(m0 - mn0), rs1 = __expf(m1 - mn1);
        float s0 = 0.f, s1 = 0.f;
#pragma unroll
        for (int ni = 0; ni < 16; ni++) {
            accs[ni][0] = __expf(accs[ni][0] - mn0);
            accs[ni][1] = __expf(accs[ni][1] - mn0);
            accs[ni][2] = __expf(accs[ni][2] - mn1);
            accs[ni][3] = __expf(accs[ni][3] - mn1);
            s0 += accs[ni][0] + accs[ni][1];
            s1 += accs[ni][2] + accs[ni][3];
        }
        s0 += __shfl_xor_sync(~0u, s0, 1);
        s0 += __shfl_xor_sync(~0u, s0, 2);
        s1 += __shfl_xor_sync(~0u, s1, 1);
        s1 += __shfl_xor_sync(~0u, s1, 2);
        l0 = l0 * rs0 + s0;
        l1 = l1 * rs1 + s1;
        m0 = mn0; m1 = mn1;
#pragma unroll
        for (int no = 0; no < 8; no++) {
            acco[no][0] *= rs0; acco[no][1] *= rs0;
            acco[no][2] *= rs1; acco[no][3] *= rs1;
        }

#pragma unroll
        for (int ks = 0; ks < 8; ks++) {
            uint32_t ap[4];
            ap[0] = packh2(accs[2 * ks][0], accs[2 * ks][1]);
            ap[1] = packh2(accs[2 * ks][2], accs[2 * ks][3]);
            ap[2] = packh2(accs[2 * ks + 1][0], accs[2 * ks + 1][1]);
            ap[3] = packh2(accs[2 * ks + 1][2], accs[2 * ks + 1][3]);
#pragma unroll
            for (int np = 0; np < 4; np++) {
                uint32_t b0, b1, b2, b3;
                ldsm4(b0, b1, b2, b3,
                      vbase + (uint32_t)((np * 16 + ((lane >> 4) << 3) +
                                          (lane & 7)) * VST + ks * 16 +
                                         ((lane >> 3) & 1) * 8) * 2);
                uint32_t bf0[2] = { b0, b1 }, bf1[2] = { b2, b3 };
                mma16816(acco[2 * np], ap, bf0);
                mma16816(acco[2 * np + 1], ap, bf1);
            }
        }
        __syncthreads();
        if (t + 2 < NT) issueKV(t & 1, t + 2);
    }

    // ---- epilogue: context + row stats export ----
    const float inv0 = 1.f / l0, inv1 = 1.f / l1;
    const int row = r0w + (lane >> 2);
#pragma unroll
    for (int no = 0; no < 8; no++) {
        int col = no * 8 + (lane & 3) * 2;
        *(__half2*)(Cb + (size_t)row * Dd + col) =
            __floats2half2_rn(acco[no][0] * inv0, acco[no][1] * inv0);
        *(__half2*)(Cb + (size_t)(row + 8) * Dd + col) =
            __floats2half2_rn(acco[no][2] * inv1, acco[no][3] * inv1);
    }
    if ((lane & 3) == 0) {
        size_t rbase = (size_t)bh * Ss + q0;
        sm[rbase + row] = m0;     sl[rbase + row] = inv0;
        sm[rbase + row + 8] = m1; sl[rbase + row + 8] = inv1;
    }
}

// ---------------------------------------------------------------------------
// Finalize (elementwise, chip-filling): ext = expf(Sh - m[row]) * il[row]
// ---------------------------------------------------------------------------
__global__ void __launch_bounds__(256) finalize_kernel(
    const __half* __restrict__ S, const float* __restrict__ sm,
    const float* __restrict__ sl, float* __restrict__ ext)
{
    const size_t row = blockIdx.x;
    const float mm = sm[row], il = sl[row];
    const __half* p = S + row * Ss;
    const int col = threadIdx.x * 4;

    __half2 h0 = *(const __half2*)(p + col);
    __half2 h1 = *(const __half2*)(p + col + 2);
    float2 f0 = __half22float2(h0), f1 = __half22float2(h1);
    float4 o;
    o.x = __expf(f0.x - mm) * il;
    o.y = __expf(f0.y - mm) * il;
    o.z = __expf(f1.x - mm) * il;
    o.w = __expf(f1.y - mm) * il;
    *(float4*)(ext + row * Ss + col) = o;
}

// ---------------------------------------------------------------------------
// Fused prologue: convert q/k/v fp32 -> fp16 (one launch)
// ---------------------------------------------------------------------------
__global__ void __launch_bounds__(256) convert_all(
    const float* __restrict__ q, const float* __restrict__ k,
    const float* __restrict__ v,
    __half* __restrict__ qh, __half* __restrict__ kh, __half* __restrict__ vh)
{
    const int which = blockIdx.x >> 13;              // 8192 blocks per tensor
    const float* X = (which == 0) ? q : (which == 1) ? k : v;
    __half* H = (which == 0) ? qh : (which == 1) ? kh : vh;
    size_t i = (size_t)(blockIdx.x & 8191) * 256 + threadIdx.x;
    float4 vv = ((const float4*)X)[i];
    *(__half2*)(H + i * 4)     = __floats2half2_rn(vv.x, vv.y);
    *(__half2*)(H + i * 4 + 2) = __floats2half2_rn(vv.z, vv.w);
}

// Fused prologue: all 6 weight transposes (one launch). 32x32 tiles.
__global__ void transpose_all(
    const float* __restrict__ wq, const float* __restrict__ wk,
    const float* __restrict__ wv, const float* __restrict__ wo,
    const float* __restrict__ w1, const float* __restrict__ w2,
    __half* __restrict__ wqT, __half* __restrict__ wkT,
    __half* __restrict__ wvT, __half* __restrict__ woT,
    __half* __restrict__ w1T, __half* __restrict__ w2T)
{
    __shared__ float t[32][33];
    const int idx = blockIdx.x;
    const float* W; __half* T; int R, C, c0, r0;
    if (idx < 4096) {
        int w = idx >> 10, tt = idx & 1023;
        W = (w == 0) ? wq : (w == 1) ? wk : (w == 2) ? wv : wo;
        T = (w == 0) ? wqT : (w == 1) ? wkT : (w == 2) ? wvT : woT;
        R = 1024; C = 1024;
        c0 = (tt & 31) * 32; r0 = (tt >> 5) * 32;
    } else if (idx < 8192) {
        int tt = idx - 4096;
        W = w1; T = w1T; R = 1024; C = 4096;
        c0 = (tt & 127) * 32; r0 = (tt >> 7) * 32;
    } else {
        int tt = idx - 8192;
        W = w2; T = w2T; R = 4096; C = 1024;
        c0 = (tt & 31) * 32; r0 = (tt >> 5) * 32;
    }
#pragma unroll
    for (int i = threadIdx.y; i < 32; i += 8)
        t[i][threadIdx.x] = W[(size_t)(r0 + i) * C + c0 + threadIdx.x];
    __syncthreads();
#pragma unroll
    for (int i = threadIdx.y; i < 32; i += 8)
        T[(size_t)(c0 + i) * R + r0 + threadIdx.x] =
            __float2half_rn(t[threadIdx.x][i]);
}

__global__ void vt_f16(const __half* __restrict__ VH, __half* __restrict__ TH)
{
    __shared__ __half t[32][33];
    const int bh = blockIdx.z, b = bh >> 4, h = bh & 15;
    const int sk0 = blockIdx.x * 32, d0 = blockIdx.y * 32;
    const __half* vh = VH + (size_t)b * Ss * Dd + h * HDIM;
#pragma unroll
    for (int i = threadIdx.y; i < 32; i += 8)
        t[i][threadIdx.x] = vh[(size_t)(sk0 + i) * Dd + d0 + threadIdx.x];
    __syncthreads();
    __half* oh = TH + (size_t)bh * HDIM * Ss;
#pragma unroll
    for (int i = threadIdx.y; i < 32; i += 8)
        oh[(size_t)(d0 + i) * Ss + sk0 + threadIdx.x] = t[threadIdx.x][i];
}

// ---------------------------------------------------------------------------
// LayerNorm kernels
// ---------------------------------------------------------------------------
__device__ __forceinline__ float block_sum(float v, float* sbuf) {
    const int lane = threadIdx.x & 31, w = threadIdx.x >> 5;
#pragma unroll
    for (int o = 16; o > 0; o >>= 1) v += __shfl_xor_sync(~0u, v, o);
    __syncthreads();
    if (lane == 0) sbuf[w] = v;
    __syncthreads();
    float s = 0.f;
#pragma unroll
    for (int i = 0; i < 8; i++) s += sbuf[i];
    return s;
}

__global__ void __launch_bounds__(256) ln_a_kernel(
    const float* __restrict__ X, const float* __restrict__ q,
    const float* __restrict__ g1, const float* __restrict__ b1,
    const float* __restrict__ g2, const float* __restrict__ b2,
    float* __restrict__ out, __half* __restrict__ OH)
{
    __shared__ float sbuf[8];
    const size_t row = blockIdx.x;
    const int col = threadIdx.x * 4;
    float4 xv = *(const float4*)(X + row * Dd + col);
    float4 qv = *(const float4*)(q + row * Dd + col);
    float t[4] = { xv.x + qv.x, xv.y + qv.y, xv.z + qv.z, xv.w + qv.w };

    float mu = block_sum(t[0] + t[1] + t[2] + t[3], sbuf) * (1.0f / Dd);
    float ss = 0.f;
#pragma unroll
    for (int i = 0; i < 4; i++) { float d = t[i] - mu; ss += d * d; }
    float var = block_sum(ss, sbuf) * (1.0f / Dd);
    float inv = rsqrtf(var + 1e-8f);

    float4 g = *(const float4*)(g1 + col);
    float4 be = *(const float4*)(b1 + col);
    float qarr[4] = { qv.x, qv.y, qv.z, qv.w };
    float garr[4] = { g.x, g.y, g.z, g.w };
    float barr[4] = { be.x, be.y, be.z, be.w };
    float t2[4];
#pragma unroll
    for (int i = 0; i < 4; i++)
        t2[i] = qarr[i] + (t[i] - mu) * inv * garr[i] + barr[i];

    float mu2 = block_sum(t2[0] + t2[1] + t2[2] + t2[3], sbuf) * (1.0f / Dd);
    float ss2 = 0.f;
#pragma unroll
    for (int i = 0; i < 4; i++) { float d = t2[i] - mu2; ss2 += d * d; }
    float var2 = block_sum(ss2, sbuf) * (1.0f / Dd);
    float inv2 = rsqrtf(var2 + 1e-6f);

    g = *(const float4*)(g2 + col);
    be = *(const float4*)(b2 + col);
    float4 o;
    o.x = (t2[0] - mu2) * inv2 * g.x + be.x;
    o.y = (t2[1] - mu2) * inv2 * g.y + be.y;
    o.z = (t2[2] - mu2) * inv2 * g.z + be.z;
    o.w = (t2[3] - mu2) * inv2 * g.w + be.w;
    *(float4*)(out + row * Dd + col) = o;
    *(__half2*)(OH + row * Dd + col)     = __floats2half2_rn(o.x, o.y);
    *(__half2*)(OH + row * Dd + col + 2) = __floats2half2_rn(o.z, o.w);
}

__global__ void __launch_bounds__(256) ln_b_kernel(
    const float* __restrict__ Z, const float* __restrict__ res,
    const float* __restrict__ g1, const float* __restrict__ b1,
    float* __restrict__ out)
{
    __shared__ float sbuf[8];
    const size_t row = blockIdx.x;
    const int col = threadIdx.x * 4;
    float4 zv = *(const float4*)(Z + row * Dd + col);
    float4 rv = *(const float4*)(res + row * Dd + col);
    float t[4] = { zv.x + rv.x, zv.y + rv.y, zv.z + rv.z, zv.w + rv.w };

    float mu = block_sum(t[0] + t[1] + t[2] + t[3], sbuf) * (1.0f / Dd);
    float ss = 0.f;
#pragma unroll
    for (int i = 0; i < 4; i++) { float d = t[i] - mu; ss += d * d; }
    float var = block_sum(ss, sbuf) * (1.0f / Dd);
    float inv = rsqrtf(var + 1e-6f);

    float4 g = *(const float4*)(g1 + col);
    float4 be = *(const float4*)(b1 + col);
    float4 o;
    o.x = (t[0] - mu) * inv * g.x + be.x;
    o.y = (t[1] - mu) * inv * g.y + be.y;
    o.z = (t[2] - mu) * inv * g.z + be.z;
    o.w = (t[3] - mu) * inv * g.w + be.w;
    *(float4*)(out + row * Dd + col) = o;
}

// ---------------------------------------------------------------------------
// kernel_launch
// ---------------------------------------------------------------------------
extern "C" void kernel_launch(void* const* d_in, const int* in_sizes, int n_in,
                              void* d_out, int out_size)
{
    const float* query = (const float*)d_in[0];
    const float* key   = (const float*)d_in[1];
    const float* value = (const float*)d_in[2];
    const float* mask  = (const float*)d_in[3];
    const float* wq = (const float*)d_in[4];
    const float* bq = (const float*)d_in[5];
    const float* wk = (const float*)d_in[6];
    const float* bk = (const float*)d_in[7];
    const float* wv = (const float*)d_in[8];
    const float* bv = (const float*)d_in[9];
    const float* wo = (const float*)d_in[10];
    const float* bo = (const float*)d_in[11];
    const float* ln_mha_g = (const float*)d_in[12];
    const float* ln_mha_b = (const float*)d_in[13];
    const float* w1 = (const float*)d_in[14];
    const float* b1 = (const float*)d_in[15];
    const float* w2 = (const float*)d_in[16];
    const float* b2 = (const float*)d_in[17];
    const float* ln_attn_g = (const float*)d_in[18];
    const float* ln_attn_b = (const float*)d_in[19];
    const float* ln_ffn_g = (const float*)d_in[20];
    const float* ln_ffn_b = (const float*)d_in[21];
    (void)in_sizes; (void)n_in;

    float* out = (float*)d_out;

    __half *qh, *kh, *vh, *Qh, *Kh, *Vh, *Vth, *cth, *aoh, *Fh, *Sh, *WT;
    float *X, *ao, *Z, *smb, *slb;
    cudaGetSymbolAddress((void**)&qh, g_qh);
    cudaGetSymbolAddress((void**)&kh, g_kh);
    cudaGetSymbolAddress((void**)&vh, g_vh);
    cudaGetSymbolAddress((void**)&Qh, g_Qh);
    cudaGetSymbolAddress((void**)&Kh, g_Kh);
    cudaGetSymbolAddress((void**)&Vh, g_Vh);
    cudaGetSymbolAddress((void**)&Vth, g_Vth);
    cudaGetSymbolAddress((void**)&cth, g_cth);
    cudaGetSymbolAddress((void**)&aoh, g_aoh);
    cudaGetSymbolAddress((void**)&Fh, g_Fh);
    cudaGetSymbolAddress((void**)&Sh, g_Sh);
    cudaGetSymbolAddress((void**)&WT, g_WT);
    cudaGetSymbolAddress((void**)&X, g_X);
    cudaGetSymbolAddress((void**)&ao, g_ao);
    cudaGetSymbolAddress((void**)&Z, g_Z);
    cudaGetSymbolAddress((void**)&smb, g_sm);
    cudaGetSymbolAddress((void**)&slb, g_sl);

    const size_t nS = (size_t)Bb * Hh * Ss * Ss;

    __half *wqT = WT;
    __half *wkT = WT + (size_t)Dd * Dd;
    __half *wvT = WT + (size_t)2 * Dd * Dd;
    __half *woT = WT + (size_t)3 * Dd * Dd;
    __half *w1T = WT + (size_t)4 * Dd * Dd;
    __half *w2T = w1T + (size_t)Dd * Ff;

    const long long main_elems = (long long)Mm * Dd;
    const long long attn_elems = (long long)nS;
    float* attn_ext = ((long long)out_size >= main_elems + attn_elems)
                          ? (out + main_elems) : nullptr;

    // BM=64 stage: 2*5120 + 2*128*80 = 30720 ; 2 stages = 61440 (3 CTAs/SM)
    const int DSZ128 = 2 * (2 * 64 * 80 + 2 * 128 * 80);
    const int FSZ = 18432 + 2 * 18432 + 2 * 17408 + 4096;  // 94208
    cudaFuncSetAttribute(gemm_ps<128,0,2>, cudaFuncAttributeMaxDynamicSharedMemorySize, DSZ128);
    cudaFuncSetAttribute(gemm_ps<128,0,0>, cudaFuncAttributeMaxDynamicSharedMemorySize, DSZ128);
    cudaFuncSetAttribute(gemm_ps<128,1,2>, cudaFuncAttributeMaxDynamicSharedMemorySize, DSZ128);
    cudaFuncSetAttribute(flash_attn, cudaFuncAttributeMaxDynamicSharedMemorySize, FSZ);

    dim3 tblk(32, 8);

    // Fused prologue
    convert_all<<<3 * 8192, 256>>>(query, key, value, qh, kh, vh);
    transpose_all<<<12288, tblk>>>(wq, wk, wv, wo, w1, w2,
                                   wqT, wkT, wvT, woT, w1T, w2T);

    // QKV projections -> fp16
    gemm_ps<128,0,2><<<dim3(Dd/128, Mm/64), 256, DSZ128>>>(
        qh, Dd, wqT, Dd, nullptr, Qh, Dd, bq, Dd);
    gemm_ps<128,0,2><<<dim3(Dd/128, Mm/64), 256, DSZ128>>>(
        kh, Dd, wkT, Dd, nullptr, Kh, Dd, bk, Dd);
    gemm_ps<128,0,2><<<dim3(Dd/128, Mm/64), 256, DSZ128>>>(
        vh, Dd, wvT, Dd, nullptr, Vh, Dd, bv, Dd);

    // V^T per head
    vt_f16<<<dim3(Ss/32, HDIM/32, Bb*Hh), tblk>>>(Vh, Vth);

    // Fused attention: scores + online softmax + PV (+ row stats export)
    flash_attn<<<dim3(Ss/128, Bb*Hh), 256, FSZ>>>(Qh, Kh, Vth, mask,
                                                  Sh, cth, smb, slb);

    // attn_weights output: elementwise using exported stats
    if (attn_ext)
        finalize_kernel<<<Bb*Hh*Ss, 256>>>(Sh, smb, slb, attn_ext);

    // O-projection -> fp32 X
    gemm_ps<128,0,0><<<dim3(Dd/128, Mm/64), 256, DSZ128>>>(
        cth, Dd, woT, Dd, X, nullptr, Dd, bo, Dd);

    // Double LayerNorm -> attn_out fp32 + fp16
    ln_a_kernel<<<Mm, 256>>>(X, query, ln_mha_g, ln_mha_b,
                             ln_attn_g, ln_attn_b, ao, aoh);

    // FFN1 -> fp16 (relu)
    gemm_ps<128,1,2><<<dim3(Ff/128, Mm/64), 256, DSZ128>>>(
        aoh, Dd, w1T, Dd, nullptr, Fh, Ff, b1, Dd);

    // FFN2 -> fp32 Z
    gemm_ps<128,0,0><<<dim3(Dd/128, Mm/64), 256, DSZ128>>>(
        Fh, Ff, w2T, Ff, Z, nullptr, Dd, b2, Ff);

    // Final LayerNorm -> main output
    ln_b_kernel<<<Mm, 256>>>(Z, ao, ln_ffn_g, ln_ffn_b, out);
}

// round 16
// speedup vs baseline: 1.0814x; 1.0814x over previous
#include <cuda_runtime.h>
#include <cuda_fp16.h>
#include <math.h>
#include <stdint.h>

#define Bb 8
#define Ss 1024
#define Dd 1024
#define Hh 16
#define HDIM 64
#define Ff 4096
#define Mm (Bb*Ss)

// ---------------------------------------------------------------------------
// Scratch (device globals). All GEMM operands single-plane fp16.
// ---------------------------------------------------------------------------
__device__ __half g_qh [(size_t)Mm*Dd];
__device__ __half g_kh [(size_t)Mm*Dd];
__device__ __half g_vh [(size_t)Mm*Dd];
__device__ __half g_Qh [(size_t)Mm*Dd];
__device__ __half g_Kh [(size_t)Mm*Dd];
__device__ __half g_Vh [(size_t)Mm*Dd];
__device__ __half g_Vth[(size_t)Bb*Hh*HDIM*Ss];
__device__ __half g_cth[(size_t)Mm*Dd];
__device__ __half g_aoh[(size_t)Mm*Dd];
__device__ __half g_Fh [(size_t)Mm*Ff];
__device__ __half g_Sh [(size_t)Bb*Hh*Ss*Ss];      // scores fp16 (post-mask)
__device__ float  g_sm [(size_t)Bb*Hh*Ss];         // per-row max
__device__ float  g_sl [(size_t)Bb*Hh*Ss];         // per-row 1/sum
__device__ __half g_WT [(size_t)(4*Dd*Dd + Dd*Ff + Ff*Dd)];
__device__ float  g_X  [(size_t)Mm*Dd];
__device__ float  g_ao [(size_t)Mm*Dd];
__device__ float  g_Z  [(size_t)Mm*Dd];

// ---------------------------------------------------------------------------
// PTX helpers
// ---------------------------------------------------------------------------
__device__ __forceinline__ uint32_t smem_u32(const void* p) {
    uint32_t a;
    asm("{ .reg .u64 t; cvta.to.shared.u64 t, %1; cvt.u32.u64 %0, t; }"
        : "=r"(a) : "l"(p));
    return a;
}
__device__ __forceinline__ void ldsm4(uint32_t& r0, uint32_t& r1, uint32_t& r2,
                                      uint32_t& r3, uint32_t addr) {
    asm volatile("ldmatrix.sync.aligned.m8n8.x4.shared.b16 {%0,%1,%2,%3}, [%4];"
                 : "=r"(r0), "=r"(r1), "=r"(r2), "=r"(r3) : "r"(addr));
}
__device__ __forceinline__ void mma16816(float* d, const uint32_t* a,
                                         const uint32_t* b) {
    asm volatile(
        "mma.sync.aligned.m16n8k16.row.col.f32.f16.f16.f32 "
        "{%0,%1,%2,%3}, {%4,%5,%6,%7}, {%8,%9}, {%0,%1,%2,%3};"
        : "+f"(d[0]), "+f"(d[1]), "+f"(d[2]), "+f"(d[3])
        : "r"(a[0]), "r"(a[1]), "r"(a[2]), "r"(a[3]), "r"(b[0]), "r"(b[1]));
}
__device__ __forceinline__ void cpa16(uint32_t dst, const void* src) {
    asm volatile("cp.async.cg.shared.global [%0], [%1], 16;"
                 :: "r"(dst), "l"(src) : "memory");
}
#define CP_COMMIT() asm volatile("cp.async.commit_group;" ::: "memory")
#define CP_WAIT0()  asm volatile("cp.async.wait_group 0;" ::: "memory")
#define CP_WAIT1()  asm volatile("cp.async.wait_group 1;" ::: "memory")

__device__ __forceinline__ uint32_t packh2(float a, float b) {
    __half2 h = __floats2half2_rn(a, b);
    return *(uint32_t*)&h;
}

// ---------------------------------------------------------------------------
// GEMM core (R14 config): C[128 x BN] = A[128,K] @ B[BN,K]^T, fp32 accum.
//   BK=64 chunks, 2-stage cp.async, 1 sync/chunk, 2 CTAs/SM.
//   Warp grid 2(m) x 4(n), warp tile 64 x (BN/4).
//   EPI: 0=+bias  1=+bias,relu ; CFMT: 0 = fp32 out ; 2 = fp16 out
// ---------------------------------------------------------------------------
template<int BN, int EPI, int CFMT>
__device__ __forceinline__ void gemm_body(
    const __half* __restrict__ Abh,   // A block base (row0 applied)
    long long lda,
    const __half* __restrict__ Bbh,   // B block base (col0 applied)
    long long ldb,
    float* __restrict__ C, __half* __restrict__ CH,
    long long ldc,
    const float* __restrict__ aux, int K,
    int row0, int col0, char* dsm)
{
    constexpr int MF = 4;
    constexpr int NF = BN / 32;
    constexpr int ABLK = 10240;          // 128 rows x 80 B
    constexpr int BBLK = BN * 80;
    constexpr int STAGE = 2 * ABLK + 2 * BBLK;

    const int tid = threadIdx.x, lane = tid & 31, wid = tid >> 5;
    const int m0w = (wid >> 2) * 64, n0w = (wid & 3) * (BN / 4);

    const uint32_t sbase = smem_u32(dsm);

    float acc[MF][NF][4];
#pragma unroll
    for (int i = 0; i < MF; i++)
#pragma unroll
        for (int j = 0; j < NF; j++)
#pragma unroll
            for (int k = 0; k < 4; k++) acc[i][j][k] = 0.f;

    auto issue = [&](int st, int k0) {
        uint32_t base = sbase + st * STAGE;
#pragma unroll
        for (int i = 0; i < 4; i++) {        // A: 128 rows x 8 16B-groups
            int q = tid + i * 256;
            int r = q >> 3, g = q & 7;
            int blk = g >> 2, gg = g & 3;
            cpa16(base + blk * ABLK + r * 80 + gg * 16,
                  Abh + (size_t)r * lda + k0 + g * 8);
        }
#pragma unroll
        for (int i = 0; i < NF; i++) {       // B: BN rows x 8 groups
            int q = tid + i * 256;
            int r = q >> 3, g = q & 7;
            int blk = g >> 2, gg = g & 3;
            cpa16(base + 2 * ABLK + blk * BBLK + r * 80 + gg * 16,
                  Bbh + (size_t)r * ldb + k0 + g * 8);
        }
        CP_COMMIT();
    };

    const int NCH = K >> 6;
    issue(0, 0);

    for (int c = 0; c < NCH; c++) {
        CP_WAIT0();
        __syncthreads();
        if (c + 1 < NCH) issue((c + 1) & 1, (c + 1) * 64);

        const uint32_t stg = sbase + (c & 1) * STAGE;
#pragma unroll
        for (int j = 0; j < 2; j++) {
            const uint32_t aAh = stg + j * ABLK;
            const uint32_t aBh = stg + 2 * ABLK + j * BBLK;
#pragma unroll
            for (int kk = 0; kk < 32; kk += 16) {
                uint32_t bh[NF][2];
#pragma unroll
                for (int np = 0; np < NF / 2; np++) {
                    uint32_t bo = (uint32_t)((n0w + np * 16 + ((lane >> 4) << 3) +
                                              (lane & 7)) * 40 +
                                             kk + ((lane >> 3) & 1) * 8) * 2;
                    ldsm4(bh[2 * np][0], bh[2 * np][1], bh[2 * np + 1][0],
                          bh[2 * np + 1][1], aBh + bo);
                }
#pragma unroll
                for (int mi = 0; mi < MF; mi++) {
                    uint32_t ao = (uint32_t)((m0w + mi * 16 + (lane & 15)) * 40 +
                                             kk + ((lane >> 4) << 3)) * 2;
                    uint32_t ah[4];
                    ldsm4(ah[0], ah[1], ah[2], ah[3], aAh + ao);
#pragma unroll
                    for (int ni = 0; ni < NF; ni++)
                        mma16816(acc[mi][ni], ah, bh[ni]);
                }
            }
        }
    }
    __syncthreads();

#pragma unroll
    for (int ni = 0; ni < NF; ni++) {
        const int col = col0 + n0w + ni * 8 + (lane & 3) * 2;
        float2 e = *(const float2*)(aux + col);
#pragma unroll
        for (int mi = 0; mi < MF; mi++) {
            const int r0g = row0 + m0w + mi * 16 + (lane >> 2);
            float* a = acc[mi][ni];
            float2 v0 = make_float2(a[0] + e.x, a[1] + e.y);
            float2 v1 = make_float2(a[2] + e.x, a[3] + e.y);
            if (EPI == 1) {
                v0.x = fmaxf(v0.x, 0.f); v0.y = fmaxf(v0.y, 0.f);
                v1.x = fmaxf(v1.x, 0.f); v1.y = fmaxf(v1.y, 0.f);
            }
            if (CFMT == 0) {
                *(float2*)(C + (size_t)r0g * ldc + col) = v0;
                *(float2*)(C + (size_t)(r0g + 8) * ldc + col) = v1;
            } else {
                *(__half2*)(CH + (size_t)r0g * ldc + col) =
                    __floats2half2_rn(v0.x, v0.y);
                *(__half2*)(CH + (size_t)(r0g + 8) * ldc + col) =
                    __floats2half2_rn(v1.x, v1.y);
            }
        }
    }
}

// Standard single-operand GEMM
template<int BN, int EPI, int CFMT>
__global__ void __launch_bounds__(256, 2) gemm_ps(
    const __half* __restrict__ AH, long long lda,
    const __half* __restrict__ BH, long long ldb,
    float* __restrict__ C, __half* __restrict__ CH, long long ldc,
    const float* __restrict__ aux, int K)
{
    extern __shared__ char dsm[];
    const int row0 = blockIdx.y * 128, col0 = blockIdx.x * BN;
    gemm_body<BN, EPI, CFMT>(AH + (size_t)row0 * lda, lda,
                             BH + (size_t)col0 * ldb, ldb,
                             C, CH, ldc, aux, K, row0, col0, dsm);
}

// Batched QKV GEMM: blockIdx.z in {0,1,2} selects (A, B, C, bias)
__global__ void __launch_bounds__(256, 2) gemm_qkv(
    const __half* __restrict__ A0, const __half* __restrict__ A1,
    const __half* __restrict__ A2,
    const __half* __restrict__ B0, const __half* __restrict__ B1,
    const __half* __restrict__ B2,
    __half* __restrict__ C0, __half* __restrict__ C1,
    __half* __restrict__ C2,
    const float* __restrict__ x0, const float* __restrict__ x1,
    const float* __restrict__ x2)
{
    extern __shared__ char dsm[];
    const int z = blockIdx.z;
    const __half* A = (z == 0) ? A0 : (z == 1) ? A1 : A2;
    const __half* B = (z == 0) ? B0 : (z == 1) ? B1 : B2;
    __half* C = (z == 0) ? C0 : (z == 1) ? C1 : C2;
    const float* aux = (z == 0) ? x0 : (z == 1) ? x1 : x2;
    const int row0 = blockIdx.y * 128, col0 = blockIdx.x * 128;
    gemm_body<128, 0, 2>(A + (size_t)row0 * Dd, Dd,
                         B + (size_t)col0 * Dd, Dd,
                         nullptr, C, Dd, aux, Dd, row0, col0, dsm);
}

// ---------------------------------------------------------------------------
// Flash attention: scores + online softmax + PV (R13/R14 proven version).
// ---------------------------------------------------------------------------
__global__ void __launch_bounds__(256, 1) flash_attn(
    const __half* __restrict__ Qh, const __half* __restrict__ Kh,
    const __half* __restrict__ Vth, const float* __restrict__ mask,
    __half* __restrict__ Sh, __half* __restrict__ cth,
    float* __restrict__ sm, float* __restrict__ sl)
{
    constexpr int TW = 128;
    constexpr int DST = 72;
    constexpr int VST = 136;

    extern __shared__ char dsm[];
    __half* Qs  = (__half*)dsm;
    __half* Ks0 = (__half*)(dsm + 18432);
    __half* Vs0 = (__half*)(dsm + 18432 + 2 * 18432);
    float* madd = (float*)(dsm + 18432 + 2 * 18432 + 2 * 17408);

    const int tid = threadIdx.x, lane = tid & 31, wid = tid >> 5;
    const int bh = blockIdx.y, b = bh >> 4, h = bh & 15;
    const int q0 = blockIdx.x * 128;

    const __half* Qb = Qh + (size_t)b * Ss * Dd + (size_t)h * HDIM + (size_t)q0 * Dd;
    const __half* Kb = Kh + (size_t)b * Ss * Dd + (size_t)h * HDIM;
    const __half* Vb = Vth + (size_t)bh * HDIM * Ss;
    __half* Shb = Sh + (size_t)bh * Ss * Ss + (size_t)q0 * Ss;
    __half* Cb  = cth + (size_t)b * Ss * Dd + (size_t)h * HDIM + (size_t)q0 * Dd;

    {
        float4 mv = *(const float4*)(mask + (size_t)b * Ss + tid * 4);
        madd[tid * 4 + 0] = (1.f - mv.x) * -10000.f;
        madd[tid * 4 + 1] = (1.f - mv.y) * -10000.f;
        madd[tid * 4 + 2] = (1.f - mv.z) * -10000.f;
        madd[tid * 4 + 3] = (1.f - mv.w) * -10000.f;
    }

    auto issueKV = [&](int st, int t) {
        __half* kd = Ks0 + st * (DST * 128);
        const __half* ks = Kb + (size_t)(t * TW) * Dd;
#pragma unroll
        for (int i = 0; i < 4; i++) {
            int q = tid + i * 256;
            int r = q >> 3, g = q & 7;
            cpa16(smem_u32(kd + r * DST + g * 8), ks + (size_t)r * Dd + g * 8);
        }
        __half* vd = Vs0 + st * (VST * 64);
#pragma unroll
        for (int i = 0; i < 4; i++) {
            int q = tid + i * 256;
            int r = q >> 4, g = q & 15;
            cpa16(smem_u32(vd + r * VST + g * 8),
                  Vb + (size_t)r * Ss + t * TW + g * 8);
        }
        CP_COMMIT();
    };

#pragma unroll
    for (int i = 0; i < 4; i++) {
        int q = tid + i * 256;
        int r = q >> 3, g = q & 7;
        cpa16(smem_u32(Qs + r * DST + g * 8), Qb + (size_t)r * Dd + g * 8);
    }
    issueKV(0, 0);
    issueKV(1, 1);

    const int r0w = wid * 16;
    const uint32_t qbase = smem_u32(Qs);

    float m0 = -1e30f, m1 = -1e30f, l0 = 0.f, l1 = 0.f;
    float acco[8][4];
#pragma unroll
    for (int i = 0; i < 8; i++)
#pragma unroll
        for (int j = 0; j < 4; j++) acco[i][j] = 0.f;

    const int NT = Ss / TW;
    for (int t = 0; t < NT; t++) {
        if (t + 1 < NT) CP_WAIT1(); else CP_WAIT0();
        __syncthreads();

        const uint32_t kbase = smem_u32(Ks0 + (t & 1) * (DST * 128));
        const uint32_t vbase = smem_u32(Vs0 + (t & 1) * (VST * 64));

        float accs[16][4];
#pragma unroll
        for (int i = 0; i < 16; i++)
#pragma unroll
            for (int j = 0; j < 4; j++) accs[i][j] = 0.f;

#pragma unroll
        for (int kk = 0; kk < 64; kk += 16) {
            uint32_t ah[4];
            ldsm4(ah[0], ah[1], ah[2], ah[3],
                  qbase + (uint32_t)((r0w + (lane & 15)) * DST + kk +
                                     ((lane >> 4) << 3)) * 2);
#pragma unroll
            for (int np = 0; np < 8; np++) {
                uint32_t b0, b1, b2, b3;
                ldsm4(b0, b1, b2, b3,
                      kbase + (uint32_t)((np * 16 + ((lane >> 4) << 3) +
                                          (lane & 7)) * DST + kk +
                                         ((lane >> 3) & 1) * 8) * 2);
                uint32_t bf0[2] = { b0, b1 }, bf1[2] = { b2, b3 };
                mma16816(accs[2 * np], ah, bf0);
                mma16816(accs[2 * np + 1], ah, bf1);
            }
        }

        float mx0 = -1e30f, mx1 = -1e30f;
#pragma unroll
        for (int ni = 0; ni < 16; ni++) {
            int col = t * TW + ni * 8 + (lane & 3) * 2;
            float e0 = madd[col], e1 = madd[col + 1];
            accs[ni][0] = accs[ni][0] * 0.125f + e0;
            accs[ni][1] = accs[ni][1] * 0.125f + e1;
            accs[ni][2] = accs[ni][2] * 0.125f + e0;
            accs[ni][3] = accs[ni][3] * 0.125f + e1;
            mx0 = fmaxf(mx0, fmaxf(accs[ni][0], accs[ni][1]));
            mx1 = fmaxf(mx1, fmaxf(accs[ni][2], accs[ni][3]));
        }
        mx0 = fmaxf(mx0, __shfl_xor_sync(~0u, mx0, 1));
        mx0 = fmaxf(mx0, __shfl_xor_sync(~0u, mx0, 2));
        mx1 = fmaxf(mx1, __shfl_xor_sync(~0u, mx1, 1));
        mx1 = fmaxf(mx1, __shfl_xor_sync(~0u, mx1, 2));

        {
            const int row = r0w + (lane >> 2);
#pragma unroll
            for (int ni = 0; ni < 16; ni++) {
                int col = t * TW + ni * 8 + (lane & 3) * 2;
                *(__half2*)(Shb + (size_t)row * Ss + col) =
                    __floats2half2_rn(accs[ni][0], accs[ni][1]);
                *(__half2*)(Shb + (size_t)(row + 8) * Ss + col) =
                    __floats2half2_rn(accs[ni][2], accs[ni][3]);
            }
        }

        float mn0 = fmaxf(m0, mx0), mn1 = fmaxf(m1, mx1);
        float rs0 = __expf(m0 - mn0), rs1 = __expf(m1 - mn1);
        float s0 = 0.f, s1 = 0.f;
#pragma unroll
        for (int ni = 0; ni < 16; ni++) {
            accs[ni][0] = __expf(accs[ni][0] - mn0);
            accs[ni][1] = __expf(accs[ni][1] - mn0);
            accs[ni][2] = __expf(accs[ni][2] - mn1);
            accs[ni][3] = __expf(accs[ni][3] - mn1);
            s0 += accs[ni][0] + accs[ni][1];
            s1 += accs[ni][2] + accs[ni][3];
        }
        s0 += __shfl_xor_sync(~0u, s0, 1);
        s0 += __shfl_xor_sync(~0u, s0, 2);
        s1 += __shfl_xor_sync(~0u, s1, 1);
        s1 += __shfl_xor_sync(~0u, s1, 2);
        l0 = l0 * rs0 + s0;
        l1 = l1 * rs1 + s1;
        m0 = mn0; m1 = mn1;
#pragma unroll
        for (int no = 0; no < 8; no++) {
            acco[no][0] *= rs0; acco[no][1] *= rs0;
            acco[no][2] *= rs1; acco[no][3] *= rs1;
        }

#pragma unroll
        for (int ks = 0; ks < 8; ks++) {
            uint32_t ap[4];
            ap[0] = packh2(accs[2 * ks][0], accs[2 * ks][1]);
            ap[1] = packh2(accs[2 * ks][2], accs[2 * ks][3]);
            ap[2] = packh2(accs[2 * ks + 1][0], accs[2 * ks + 1][1]);
            ap[3] = packh2(accs[2 * ks + 1][2], accs[2 * ks + 1][3]);
#pragma unroll
            for (int np = 0; np < 4; np++) {
                uint32_t b0, b1, b2, b3;
                ldsm4(b0, b1, b2, b3,
                      vbase + (uint32_t)((np * 16 + ((lane >> 4) << 3) +
                                          (lane & 7)) * VST + ks * 16 +
                                         ((lane >> 3) & 1) * 8) * 2);
                uint32_t bf0[2] = { b0, b1 }, bf1[2] = { b2, b3 };
                mma16816(acco[2 * np], ap, bf0);
                mma16816(acco[2 * np + 1], ap, bf1);
            }
        }
        __syncthreads();
        if (t + 2 < NT) issueKV(t & 1, t + 2);
    }

    const float inv0 = 1.f / l0, inv1 = 1.f / l1;
    const int row = r0w + (lane >> 2);
#pragma unroll
    for (int no = 0; no < 8; no++) {
        int col = no * 8 + (lane & 3) * 2;
        *(__half2*)(Cb + (size_t)row * Dd + col) =
            __floats2half2_rn(acco[no][0] * inv0, acco[no][1] * inv0);
        *(__half2*)(Cb + (size_t)(row + 8) * Dd + col) =
            __floats2half2_rn(acco[no][2] * inv1, acco[no][3] * inv1);
    }
    if ((lane & 3) == 0) {
        size_t rbase = (size_t)bh * Ss + q0;
        sm[rbase + row] = m0;     sl[rbase + row] = inv0;
        sm[rbase + row + 8] = m1; sl[rbase + row + 8] = inv1;
    }
}

// ---------------------------------------------------------------------------
// Finalize (elementwise): ext = expf(Sh - m[row]) * il[row]
// ---------------------------------------------------------------------------
__global__ void __launch_bounds__(256) finalize_kernel(
    const __half* __restrict__ S, const float* __restrict__ sm,
    const float* __restrict__ sl, float* __restrict__ ext)
{
    const size_t row = blockIdx.x;
    const float mm = sm[row], il = sl[row];
    const __half* p = S + row * Ss;
    const int col = threadIdx.x * 4;

    __half2 h0 = *(const __half2*)(p + col);
    __half2 h1 = *(const __half2*)(p + col + 2);
    float2 f0 = __half22float2(h0), f1 = __half22float2(h1);
    float4 o;
    o.x = __expf(f0.x - mm) * il;
    o.y = __expf(f0.y - mm) * il;
    o.z = __expf(f1.x - mm) * il;
    o.w = __expf(f1.y - mm) * il;
    *(float4*)(ext + row * Ss + col) = o;
}

// ---------------------------------------------------------------------------
// Fused prologue kernels
// ---------------------------------------------------------------------------
__global__ void __launch_bounds__(256) convert_all(
    const float* __restrict__ q, const float* __restrict__ k,
    const float* __restrict__ v,
    __half* __restrict__ qh, __half* __restrict__ kh, __half* __restrict__ vh)
{
    const int which = blockIdx.x >> 13;
    const float* X = (which == 0) ? q : (which == 1) ? k : v;
    __half* H = (which == 0) ? qh : (which == 1) ? kh : vh;
    size_t i = (size_t)(blockIdx.x & 8191) * 256 + threadIdx.x;
    float4 vv = ((const float4*)X)[i];
    *(__half2*)(H + i * 4)     = __floats2half2_rn(vv.x, vv.y);
    *(__half2*)(H + i * 4 + 2) = __floats2half2_rn(vv.z, vv.w);
}

__global__ void transpose_all(
    const float* __restrict__ wq, const float* __restrict__ wk,
    const float* __restrict__ wv, const float* __restrict__ wo,
    const float* __restrict__ w1, const float* __restrict__ w2,
    __half* __restrict__ wqT, __half* __restrict__ wkT,
    __half* __restrict__ wvT, __half* __restrict__ woT,
    __half* __restrict__ w1T, __half* __restrict__ w2T)
{
    __shared__ float t[32][33];
    const int idx = blockIdx.x;
    const float* W; __half* T; int R, C, c0, r0;
    if (idx < 4096) {
        int w = idx >> 10, tt = idx & 1023;
        W = (w == 0) ? wq : (w == 1) ? wk : (w == 2) ? wv : wo;
        T = (w == 0) ? wqT : (w == 1) ? wkT : (w == 2) ? wvT : woT;
        R = 1024; C = 1024;
        c0 = (tt & 31) * 32; r0 = (tt >> 5) * 32;
    } else if (idx < 8192) {
        int tt = idx - 4096;
        W = w1; T = w1T; R = 1024; C = 4096;
        c0 = (tt & 127) * 32; r0 = (tt >> 7) * 32;
    } else {
        int tt = idx - 8192;
        W = w2; T = w2T; R = 4096; C = 1024;
        c0 = (tt & 31) * 32; r0 = (tt >> 5) * 32;
    }
#pragma unroll
    for (int i = threadIdx.y; i < 32; i += 8)
        t[i][threadIdx.x] = W[(size_t)(r0 + i) * C + c0 + threadIdx.x];
    __syncthreads();
#pragma unroll
    for (int i = threadIdx.y; i < 32; i += 8)
        T[(size_t)(c0 + i) * R + r0 + threadIdx.x] =
            __float2half_rn(t[threadIdx.x][i]);
}

__global__ void vt_f16(const __half* __restrict__ VH, __half* __restrict__ TH)
{
    __shared__ __half t[32][33];
    const int bh = blockIdx.z, b = bh >> 4, h = bh & 15;
    const int sk0 = blockIdx.x * 32, d0 = blockIdx.y * 32;
    const __half* vh = VH + (size_t)b * Ss * Dd + h * HDIM;
#pragma unroll
    for (int i = threadIdx.y; i < 32; i += 8)
        t[i][threadIdx.x] = vh[(size_t)(sk0 + i) * Dd + d0 + threadIdx.x];
    __syncthreads();
    __half* oh = TH + (size_t)bh * HDIM * Ss;
#pragma unroll
    for (int i = threadIdx.y; i < 32; i += 8)
        oh[(size_t)(d0 + i) * Ss + sk0 + threadIdx.x] = t[threadIdx.x][i];
}

// ---------------------------------------------------------------------------
// LayerNorm kernels
// ---------------------------------------------------------------------------
__device__ __forceinline__ float block_sum(float v, float* sbuf) {
    const int lane = threadIdx.x & 31, w = threadIdx.x >> 5;
#pragma unroll
    for (int o = 16; o > 0; o >>= 1) v += __shfl_xor_sync(~0u, v, o);
    __syncthreads();
    if (lane == 0) sbuf[w] = v;
    __syncthreads();
    float s = 0.f;
#pragma unroll
    for (int i = 0; i < 8; i++) s += sbuf[i];
    return s;
}

__global__ void __launch_bounds__(256) ln_a_kernel(
    const float* __restrict__ X, const float* __restrict__ q,
    const float* __restrict__ g1, const float* __restrict__ b1,
    const float* __restrict__ g2, const float* __restrict__ b2,
    float* __restrict__ out, __half* __restrict__ OH)
{
    __shared__ float sbuf[8];
    const size_t row = blockIdx.x;
    const int col = threadIdx.x * 4;
    float4 xv = *(const float4*)(X + row * Dd + col);
    float4 qv = *(const float4*)(q + row * Dd + col);
    float t[4] = { xv.x + qv.x, xv.y + qv.y, xv.z + qv.z, xv.w + qv.w };

    float mu = block_sum(t[0] + t[1] + t[2] + t[3], sbuf) * (1.0f / Dd);
    float ss = 0.f;
#pragma unroll
    for (int i = 0; i < 4; i++) { float d = t[i] - mu; ss += d * d; }
    float var = block_sum(ss, sbuf) * (1.0f / Dd);
    float inv = rsqrtf(var + 1e-8f);

    float4 g = *(const float4*)(g1 + col);
    float4 be = *(const float4*)(b1 + col);
    float qarr[4] = { qv.x, qv.y, qv.z, qv.w };
    float garr[4] = { g.x, g.y, g.z, g.w };
    float barr[4] = { be.x, be.y, be.z, be.w };
    float t2[4];
#pragma unroll
    for (int i = 0; i < 4; i++)
        t2[i] = qarr[i] + (t[i] - mu) * inv * garr[i] + barr[i];

    float mu2 = block_sum(t2[0] + t2[1] + t2[2] + t2[3], sbuf) * (1.0f / Dd);
    float ss2 = 0.f;
#pragma unroll
    for (int i = 0; i < 4; i++) { float d = t2[i] - mu2; ss2 += d * d; }
    float var2 = block_sum(ss2, sbuf) * (1.0f / Dd);
    float inv2 = rsqrtf(var2 + 1e-6f);

    g = *(const float4*)(g2 + col);
    be = *(const float4*)(b2 + col);
    float4 o;
    o.x = (t2[0] - mu2) * inv2 * g.x + be.x;
    o.y = (t2[1] - mu2) * inv2 * g.y + be.y;
    o.z = (t2[2] - mu2) * inv2 * g.z + be.z;
    o.w = (t2[3] - mu2) * inv2 * g.w + be.w;
    *(float4*)(out + row * Dd + col) = o;
    *(__half2*)(OH + row * Dd + col)     = __floats2half2_rn(o.x, o.y);
    *(__half2*)(OH + row * Dd + col + 2) = __floats2half2_rn(o.z, o.w);
}

__global__ void __launch_bounds__(256) ln_b_kernel(
    const float* __restrict__ Z, const float* __restrict__ res,
    const float* __restrict__ g1, const float* __restrict__ b1,
    float* __restrict__ out)
{
    __shared__ float sbuf[8];
    const size_t row = blockIdx.x;
    const int col = threadIdx.x * 4;
    float4 zv = *(const float4*)(Z + row * Dd + col);
    float4 rv = *(const float4*)(res + row * Dd + col);
    float t[4] = { zv.x + rv.x, zv.y + rv.y, zv.z + rv.z, zv.w + rv.w };

    float mu = block_sum(t[0] + t[1] + t[2] + t[3], sbuf) * (1.0f / Dd);
    float ss = 0.f;
#pragma unroll
    for (int i = 0; i < 4; i++) { float d = t[i] - mu; ss += d * d; }
    float var = block_sum(ss, sbuf) * (1.0f / Dd);
    float inv = rsqrtf(var + 1e-6f);

    float4 g = *(const float4*)(g1 + col);
    float4 be = *(const float4*)(b1 + col);
    float4 o;
    o.x = (t[0] - mu) * inv * g.x + be.x;
    o.y = (t[1] - mu) * inv * g.y + be.y;
    o.z = (t[2] - mu) * inv * g.z + be.z;
    o.w = (t[3] - mu) * inv * g.w + be.w;
    *(float4*)(out + row * Dd + col) = o;
}

// ---------------------------------------------------------------------------
// kernel_launch
// ---------------------------------------------------------------------------
extern "C" void kernel_launch(void* const* d_in, const int* in_sizes, int n_in,
                              void* d_out, int out_size)
{
    const float* query = (const float*)d_in[0];
    const float* key   = (const float*)d_in[1];
    const float* value = (const float*)d_in[2];
    const float* mask  = (const float*)d_in[3];
    const float* wq = (const float*)d_in[4];
    const float* bq = (const float*)d_in[5];
    const float* wk = (const float*)d_in[6];
    const float* bk = (const float*)d_in[7];
    const float* wv = (const float*)d_in[8];
    const float* bv = (const float*)d_in[9];
    const float* wo = (const float*)d_in[10];
    const float* bo = (const float*)d_in[11];
    const float* ln_mha_g = (const float*)d_in[12];
    const float* ln_mha_b = (const float*)d_in[13];
    const float* w1 = (const float*)d_in[14];
    const float* b1 = (const float*)d_in[15];
    const float* w2 = (const float*)d_in[16];
    const float* b2 = (const float*)d_in[17];
    const float* ln_attn_g = (const float*)d_in[18];
    const float* ln_attn_b = (const float*)d_in[19];
    const float* ln_ffn_g = (const float*)d_in[20];
    const float* ln_ffn_b = (const float*)d_in[21];
    (void)in_sizes; (void)n_in;

    float* out = (float*)d_out;

    __half *qh, *kh, *vh, *Qh, *Kh, *Vh, *Vth, *cth, *aoh, *Fh, *Sh, *WT;
    float *X, *ao, *Z, *smb, *slb;
    cudaGetSymbolAddress((void**)&qh, g_qh);
    cudaGetSymbolAddress((void**)&kh, g_kh);
    cudaGetSymbolAddress((void**)&vh, g_vh);
    cudaGetSymbolAddress((void**)&Qh, g_Qh);
    cudaGetSymbolAddress((void**)&Kh, g_Kh);
    cudaGetSymbolAddress((void**)&Vh, g_Vh);
    cudaGetSymbolAddress((void**)&Vth, g_Vth);
    cudaGetSymbolAddress((void**)&cth, g_cth);
    cudaGetSymbolAddress((void**)&aoh, g_aoh);
    cudaGetSymbolAddress((void**)&Fh, g_Fh);
    cudaGetSymbolAddress((void**)&Sh, g_Sh);
    cudaGetSymbolAddress((void**)&WT, g_WT);
    cudaGetSymbolAddress((void**)&X, g_X);
    cudaGetSymbolAddress((void**)&ao, g_ao);
    cudaGetSymbolAddress((void**)&Z, g_Z);
    cudaGetSymbolAddress((void**)&smb, g_sm);
    cudaGetSymbolAddress((void**)&slb, g_sl);

    const size_t nS = (size_t)Bb * Hh * Ss * Ss;

    __half *wqT = WT;
    __half *wkT = WT + (size_t)Dd * Dd;
    __half *wvT = WT + (size_t)2 * Dd * Dd;
    __half *woT = WT + (size_t)3 * Dd * Dd;
    __half *w1T = WT + (size_t)4 * Dd * Dd;
    __half *w2T = w1T + (size_t)Dd * Ff;

    const long long main_elems = (long long)Mm * Dd;
    const long long attn_elems = (long long)nS;
    float* attn_ext = ((long long)out_size >= main_elems + attn_elems)
                          ? (out + main_elems) : nullptr;

    // BK=64 stage: 2*10240 + 2*128*80 = 40960 ; 2 stages = 81920 (2 CTAs/SM)
    const int DSZ128 = 2 * (2 * 10240 + 2 * 128 * 80);
    const int FSZ = 18432 + 2 * 18432 + 2 * 17408 + 4096;  // 94208
    cudaFuncSetAttribute(gemm_qkv, cudaFuncAttributeMaxDynamicSharedMemorySize, DSZ128);
    cudaFuncSetAttribute(gemm_ps<128,0,0>, cudaFuncAttributeMaxDynamicSharedMemorySize, DSZ128);
    cudaFuncSetAttribute(gemm_ps<128,1,2>, cudaFuncAttributeMaxDynamicSharedMemorySize, DSZ128);
    cudaFuncSetAttribute(flash_attn, cudaFuncAttributeMaxDynamicSharedMemorySize, FSZ);

    dim3 tblk(32, 8);

    // Fused prologue
    convert_all<<<3 * 8192, 256>>>(query, key, value, qh, kh, vh);
    transpose_all<<<12288, tblk>>>(wq, wk, wv, wo, w1, w2,
                                   wqT, wkT, wvT, woT, w1T, w2T);

    // QKV projections: single batched launch (z = 0/1/2)
    gemm_qkv<<<dim3(Dd/128, Mm/128, 3), 256, DSZ128>>>(
        qh, kh, vh, wqT, wkT, wvT, Qh, Kh, Vh, bq, bk, bv);

    // V^T per head
    vt_f16<<<dim3(Ss/32, HDIM/32, Bb*Hh), tblk>>>(Vh, Vth);

    // Fused attention: scores + online softmax + PV (+ row stats export)
    flash_attn<<<dim3(Ss/128, Bb*Hh), 256, FSZ>>>(Qh, Kh, Vth, mask,
                                                  Sh, cth, smb, slb);

    // attn_weights output: elementwise using exported stats
    if (attn_ext)
        finalize_kernel<<<Bb*Hh*Ss, 256>>>(Sh, smb, slb, attn_ext);

    // O-projection -> fp32 X
    gemm_ps<128,0,0><<<dim3(Dd/128, Mm/128), 256, DSZ128>>>(
        cth, Dd, woT, Dd, X, nullptr, Dd, bo, Dd);

    // Double LayerNorm -> attn_out fp32 + fp16
    ln_a_kernel<<<Mm, 256>>>(X, query, ln_mha_g, ln_mha_b,
                             ln_attn_g, ln_attn_b, ao, aoh);

    // FFN1 -> fp16 (relu)
    gemm_ps<128,1,2><<<dim3(Ff/128, Mm/128), 256, DSZ128>>>(
        aoh, Dd, w1T, Dd, nullptr, Fh, Ff, b1, Dd);

    // FFN2 -> fp32 Z
    gemm_ps<128,0,0><<<dim3(Dd/128, Mm/128), 256, DSZ128>>>(
        Fh, Ff, w2T, Ff, Z, nullptr, Dd, b2, Ff);

    // Final LayerNorm -> main output
    ln_b_kernel<<<Mm, 256>>>(Z, ao, ln_ffn_g, ln_ffn_b, out);
}